// round 3
// baseline (speedup 1.0000x reference)
#include <cuda_runtime.h>
#include <cstdint>

// Persistent LSTM rollout. B=8192, T=64, F=64, ORDER=16, K=256 (Z=1024).
// 147 CTAs x 512 threads; CTA owns 56 rows for all 64 steps.
// 8 row-groups (7 rows) x 64 unit-pair threads; fma.rn.f32x2 packed math.
// Smem: A[56][592] = x(64)|yp(16)|h_par0(256)|h_par1(256); C[56][256]; Dw[256].

#define RPC   56
#define PITCH 592
#define NCTA  147
#define NTHR  512
typedef unsigned long long ull;

#define SM_A   0
#define SM_C   (RPC*PITCH)
#define SM_D   (SM_C + RPC*256)
#define SM_FLOATS (SM_D + 256)

__device__ __forceinline__ ull splat2(float f) {
    unsigned u = __float_as_uint(f); ull r;
    asm("mov.b64 %0, {%1, %1};" : "=l"(r) : "r"(u));
    return r;
}
__device__ __forceinline__ void fma2(ull& d, ull a, ull b) {
    asm("fma.rn.f32x2 %0, %1, %2, %0;" : "+l"(d) : "l"(a), "l"(b));
}
__device__ __forceinline__ void unpack2(ull v, float& lo, float& hi) {
    unsigned a, b;
    asm("mov.b64 {%0, %1}, %2;" : "=r"(a), "=r"(b) : "l"(v));
    lo = __uint_as_float(a); hi = __uint_as_float(b);
}
__device__ __forceinline__ float fex2(float x) {
    float r; asm("ex2.approx.f32 %0, %1;" : "=f"(r) : "f"(x)); return r;
}
__device__ __forceinline__ float frcp(float x) {
    float r; asm("rcp.approx.f32 %0, %1;" : "=f"(r) : "f"(x));
    return fmaf(r, fmaf(-x, r, 1.0f), r);
}
__device__ __forceinline__ float sig_(float x) {
    x = fminf(30.f, fmaxf(-30.f, x));
    return frcp(1.0f + fex2(-1.4426950408889634f * x));
}
__device__ __forceinline__ float tanh_(float x) {
    x = fminf(30.f, fmaxf(-30.f, x));
    return fmaf(2.0f, frcp(1.0f + fex2(-2.8853900817779268f * x)), -1.0f);
}

__global__ void __launch_bounds__(NTHR, 1)
lstm_roll(const float* __restrict__ x, const float* __restrict__ y0,
          const float* __restrict__ Wk, const float* __restrict__ Wr,
          const float* __restrict__ bias, const float* __restrict__ dw,
          const float* __restrict__ db, float* __restrict__ out)
{
    extern __shared__ float sm[];
    float* As = sm + SM_A;
    float* Cs = sm + SM_C;
    float* Ds = sm + SM_D;

    const int tid   = threadIdx.x;
    const int lane  = tid & 31;
    const int wrp   = tid >> 5;
    const int rbase = (tid >> 6) * 7;        // row-group base (0..49)
    const int pidx  = tid & 63;              // unit pair within half
    const int colA  = 2 * pidx;              // units 0..127
    const int colB  = 128 + 2 * pidx;        // units 128..255
    const long rowg0 = (long)blockIdx.x * RPC;

    // ---- init state ----
    for (int i = tid; i < RPC * 256; i += NTHR) Cs[i] = 0.f;
    for (int i = tid; i < RPC * 512; i += NTHR) {
        int r = i >> 9, j = i & 511;
        As[r * PITCH + 80 + j] = 0.f;
    }
    for (int i = tid; i < RPC * 16; i += NTHR) {
        int r = i >> 4, j = i & 15;
        long gr = rowg0 + r;
        As[r * PITCH + 64 + j] = (gr < 8192) ? y0[gr * 16 + j] : 0.f;
    }
    if (tid < 256) Ds[tid] = dw[tid];
    const float dbias = db[0];

    ull biasA[4], biasB[4];
#pragma unroll
    for (int g = 0; g < 4; ++g) {
        biasA[g] = *(const ull*)(bias + g * 256 + colA);
        biasB[g] = *(const ull*)(bias + g * 256 + colB);
    }
    __syncthreads();

    for (int t = 0; t < 64; ++t) {
        const int cur = t & 1, nxt = cur ^ 1;

        // ---- stage x[:, t, :] into As[:,0..63] (float4) ----
        for (int i = tid; i < RPC * 16; i += NTHR) {
            int r = i >> 4, q = i & 15;
            long gr = rowg0 + r;
            float4 v = make_float4(0.f, 0.f, 0.f, 0.f);
            if (gr < 8192) v = *(const float4*)(x + (gr * 64 + t) * 64 + q * 4);
            *(float4*)(As + r * PITCH + q * 4) = v;
        }
        __syncthreads();

        // ---- two unit-half passes ----
#pragma unroll
        for (int pass = 0; pass < 2; ++pass) {
            const int col = pass ? colB : colA;
            ull acc[7][4];
#pragma unroll
            for (int ri = 0; ri < 7; ++ri) {
#pragma unroll
                for (int g = 0; g < 4; ++g)
                    acc[ri][g] = pass ? biasB[g] : biasA[g];
            }
            // input part: k = 0..79 over Wk
            {
                const float* w  = Wk + col;
                const float* a0 = As + rbase * PITCH;
#pragma unroll 2
                for (int k = 0; k < 80; ++k) {
                    ull w0 = *(const ull*)(w);
                    ull w1 = *(const ull*)(w + 256);
                    ull w2 = *(const ull*)(w + 512);
                    ull w3 = *(const ull*)(w + 768);
                    w += 1024;
#pragma unroll
                    for (int ri = 0; ri < 7; ++ri) {
                        ull a = splat2(a0[ri * PITCH + k]);
                        fma2(acc[ri][0], a, w0);
                        fma2(acc[ri][1], a, w1);
                        fma2(acc[ri][2], a, w2);
                        fma2(acc[ri][3], a, w3);
                    }
                }
            }
            // recurrent part: k = 0..255 over Wr, h from parity 'cur'
            {
                const float* w  = Wr + col;
                const float* a0 = As + rbase * PITCH + 80 + cur * 256;
#pragma unroll 2
                for (int k = 0; k < 256; ++k) {
                    ull w0 = *(const ull*)(w);
                    ull w1 = *(const ull*)(w + 256);
                    ull w2 = *(const ull*)(w + 512);
                    ull w3 = *(const ull*)(w + 768);
                    w += 1024;
#pragma unroll
                    for (int ri = 0; ri < 7; ++ri) {
                        ull a = splat2(a0[ri * PITCH + k]);
                        fma2(acc[ri][0], a, w0);
                        fma2(acc[ri][1], a, w1);
                        fma2(acc[ri][2], a, w2);
                        fma2(acc[ri][3], a, w3);
                    }
                }
            }
            // gates + state update for (7 rows) x (2 units)
#pragma unroll
            for (int ri = 0; ri < 7; ++ri) {
                const int r = rbase + ri;
                float i0, i1, f0, f1, g0, g1, o0, o1;
                unpack2(acc[ri][0], i0, i1);
                unpack2(acc[ri][1], f0, f1);
                unpack2(acc[ri][2], g0, g1);
                unpack2(acc[ri][3], o0, o1);
                float2 c = *(float2*)(Cs + r * 256 + col);
                float cn0 = sig_(f0) * c.x + sig_(i0) * tanh_(g0);
                float cn1 = sig_(f1) * c.y + sig_(i1) * tanh_(g1);
                float h0 = sig_(o0) * tanh_(cn0);
                float h1 = sig_(o1) * tanh_(cn1);
                *(float2*)(Cs + r * 256 + col) = make_float2(cn0, cn1);
                *(float2*)(As + r * PITCH + 80 + nxt * 256 + col) = make_float2(h0, h1);
            }
        }
        __syncthreads();

        // ---- dense head + output + yp shift ----
        for (int rr = wrp; rr < RPC; rr += 16) {
            const float* h = As + rr * PITCH + 80 + nxt * 256;
            float s = 0.f;
#pragma unroll
            for (int j = 0; j < 8; ++j)
                s += h[lane + 32 * j] * Ds[lane + 32 * j];
#pragma unroll
            for (int off = 16; off; off >>= 1)
                s += __shfl_xor_sync(0xffffffffu, s, off);
            if (lane == 0) {
                float pred = s + dbias;
                long gr = rowg0 + rr;
                if (gr < 8192) out[gr * 64 + t] = pred;
                float* yp = As + rr * PITCH + 64;
#pragma unroll
                for (int j = 14; j >= 0; --j) yp[j + 1] = yp[j];
                yp[0] = pred;
            }
        }
        // next iteration's x-stage touches only cols 0..63; no race with yp/h.
    }
}

extern "C" void kernel_launch(void* const* d_in, const int* in_sizes, int n_in,
                              void* d_out, int out_size) {
    const float* x    = (const float*)d_in[0];
    const float* y0   = (const float*)d_in[1];
    const float* Wk   = (const float*)d_in[2];
    const float* Wr   = (const float*)d_in[3];
    const float* bias = (const float*)d_in[4];
    const float* dw   = (const float*)d_in[5];
    const float* db   = (const float*)d_in[6];
    float* out = (float*)d_out;

    static int smem_set = 0;
    const int smem_bytes = SM_FLOATS * 4;
    if (!smem_set) {
        cudaFuncSetAttribute(lstm_roll,
                             cudaFuncAttributeMaxDynamicSharedMemorySize,
                             smem_bytes);
        smem_set = 1;
    }
    lstm_roll<<<NCTA, NTHR, smem_bytes>>>(x, y0, Wk, Wr, bias, dw, db, out);
}

// round 5
// speedup vs baseline: 1.5063x; 1.5063x over previous
#include <cuda_runtime.h>

// LSTM rollout v2: row-pair-packed f32x2 with pre-splatted weights.
// B=8192, T=64, F=64, ORD=16, K=256. 147 CTAs x 512 thr, 56 rows/CTA.
// Thread = (row-group rg 0..3) x (unit-thread c 0..127); 2 passes cover 256 units.
// acc[7 rowpairs][4 gates] as packed f32x2 {row_even, row_odd}.

#define NCTA 147
#define NTHR 512
#define RPC  56
#define PIT  58
typedef unsigned long long ull;

__device__ ull g_Ws[336 * 1024];   // [k][u][g] pre-splatted {w,w}
__device__ ull g_Bs[1024];         // [u][g] pre-splatted bias

#define AS_F (592 * PIT)           // rows: x 0..63 | yp 64..79 | h0 80..335 | h1 336..591
#define CS_F (256 * PIT)           // c state: [u][row]
#define SM_FLOATS (AS_F + CS_F + 256)

__device__ __forceinline__ ull splat2(float f) {
    unsigned u = __float_as_uint(f); ull r;
    asm("mov.b64 %0, {%1, %1};" : "=l"(r) : "r"(u));
    return r;
}
__device__ __forceinline__ void fma2(ull& d, ull a, ull b) {
    asm("fma.rn.f32x2 %0, %1, %2, %0;" : "+l"(d) : "l"(a), "l"(b));
}
__device__ __forceinline__ void unpack2(ull v, float& lo, float& hi) {
    unsigned a, b;
    asm("mov.b64 {%0, %1}, %2;" : "=r"(a), "=r"(b) : "l"(v));
    lo = __uint_as_float(a); hi = __uint_as_float(b);
}
__device__ __forceinline__ float fex2(float x) {
    float r; asm("ex2.approx.f32 %0, %1;" : "=f"(r) : "f"(x)); return r;
}
__device__ __forceinline__ float frcp(float x) {
    float r; asm("rcp.approx.f32 %0, %1;" : "=f"(r) : "f"(x));
    return fmaf(r, fmaf(-x, r, 1.0f), r);
}
__device__ __forceinline__ float sig_(float x) {
    x = fminf(30.f, fmaxf(-30.f, x));
    return frcp(1.0f + fex2(-1.4426950408889634f * x));
}
__device__ __forceinline__ float tanh_(float x) {
    x = fminf(30.f, fmaxf(-30.f, x));
    return fmaf(2.0f, frcp(1.0f + fex2(-2.8853900817779268f * x)), -1.0f);
}

// one k-step: 2 LDG.128 + 7 LDS.64 + 28 FFMA2
__device__ __forceinline__ void kstep(ull (&acc)[7][4], const ull* __restrict__ wp,
                                      const float* __restrict__ arow) {
    ulonglong2 w01 = *(const ulonglong2*)(wp);
    ulonglong2 w23 = *(const ulonglong2*)(wp + 2);
#pragma unroll
    for (int j = 0; j < 7; ++j) {
        ull a = *(const ull*)(arow + 2 * j);
        fma2(acc[j][0], a, w01.x);
        fma2(acc[j][1], a, w01.y);
        fma2(acc[j][2], a, w23.x);
        fma2(acc[j][3], a, w23.y);
    }
}

__global__ void presplat(const float* __restrict__ Wk, const float* __restrict__ Wr,
                         const float* __restrict__ bias) {
    int k = blockIdx.x;                 // 0..335
    int col = threadIdx.x;              // 0..1023 (coalesced read)
    int g = col >> 8, u = col & 255;
    float v = (k < 80) ? Wk[k * 1024 + col] : Wr[(k - 80) * 1024 + col];
    g_Ws[k * 1024 + u * 4 + g] = splat2(v);
    if (k == 0) g_Bs[u * 4 + g] = splat2(bias[col]);
}

__global__ void __launch_bounds__(NTHR, 1)
lstm_roll(const float* __restrict__ x, const float* __restrict__ y0,
          const float* __restrict__ dw, const float* __restrict__ db,
          float* __restrict__ out)
{
    extern __shared__ float sm[];
    float* As  = sm;
    float* Cs  = sm + AS_F;
    float* Red = sm + AS_F + CS_F;

    const int tid  = threadIdx.x;
    const int lane = tid & 31;
    const int wrp  = tid >> 5;
    const int c    = tid & 127;        // unit-thread
    const int rg   = tid >> 7;         // row-group 0..3
    const int rg14 = rg * 14;
    const long rowg0 = (long)blockIdx.x * RPC;

    // ---- init: zero h (both parities) and c; load yp circular init ----
    for (int i = tid; i < CS_F; i += NTHR) Cs[i] = 0.f;
    for (int i = tid; i < 512 * PIT; i += NTHR) As[80 * PIT + i] = 0.f;
    for (int i = tid; i < RPC * 16; i += NTHR) {
        int r = i >> 4, j = i & 15;
        long gr = rowg0 + r;
        // at step t, logical yp[j] read from slot (t-1-j)&15; init slot 15-j = y0[j]
        As[(64 + (15 - j)) * PIT + r] = (gr < 8192) ? y0[gr * 16 + j] : 0.f;
    }
    const float dw0 = dw[c], dw1 = dw[128 + c];
    const float db0 = db[0];
    __syncthreads();

    for (int t = 0; t < 64; ++t) {
        const int cur = t & 1, nxt = cur ^ 1;

        // ---- stage x[:, t, :] transposed into As rows 0..63 ----
        for (int i = tid; i < RPC * 16; i += NTHR) {
            int r = i >> 4, q4 = i & 15;
            long gr = rowg0 + r;
            float4 v = make_float4(0.f, 0.f, 0.f, 0.f);
            if (gr < 8192) v = *(const float4*)(x + (gr * 64 + t) * 64 + q4 * 4);
            As[(q4 * 4 + 0) * PIT + r] = v.x;
            As[(q4 * 4 + 1) * PIT + r] = v.y;
            As[(q4 * 4 + 2) * PIT + r] = v.z;
            As[(q4 * 4 + 3) * PIT + r] = v.w;
        }
        __syncthreads();

        float ph[14];
#pragma unroll
        for (int j = 0; j < 14; ++j) ph[j] = 0.f;

#pragma unroll
        for (int pass = 0; pass < 2; ++pass) {
            const int u = pass * 128 + c;
            const ull* wb = g_Ws + u * 4;
            ull acc[7][4];
            {
                ulonglong2 b01 = *(const ulonglong2*)(g_Bs + u * 4);
                ulonglong2 b23 = *(const ulonglong2*)(g_Bs + u * 4 + 2);
#pragma unroll
                for (int j = 0; j < 7; ++j) {
                    acc[j][0] = b01.x; acc[j][1] = b01.y;
                    acc[j][2] = b23.x; acc[j][3] = b23.y;
                }
            }
            const float* ab = As + rg14;

            // x segment: k = 0..63
#pragma unroll 4
            for (int k = 0; k < 64; ++k)
                kstep(acc, wb + (size_t)k * 1024, ab + k * PIT);
            // yp segment: k = 64..79, circular slots
#pragma unroll
            for (int j = 0; j < 16; ++j) {
                int row = 64 + ((t - 1 - j) & 15);
                kstep(acc, wb + (size_t)(64 + j) * 1024, ab + row * PIT);
            }
            // h segment: k = 80..335 from parity 'cur'
            {
                const float* hb = ab + (80 + cur * 256) * PIT;
                const ull* wh = wb + (size_t)80 * 1024;
#pragma unroll 4
                for (int k = 0; k < 256; ++k)
                    kstep(acc, wh + (size_t)k * 1024, hb + k * PIT);
            }

            // ---- gates + state update (unit u, 14 rows) ----
            const float dwu = pass ? dw1 : dw0;
            float* crow = Cs + u * PIT + rg14;
            float* hrow = As + (80 + nxt * 256 + u) * PIT + rg14;
#pragma unroll
            for (int j = 0; j < 7; ++j) {
                float i0, i1, f0, f1, g0, g1, o0, o1;
                unpack2(acc[j][0], i0, i1);
                unpack2(acc[j][1], f0, f1);
                unpack2(acc[j][2], g0, g1);
                unpack2(acc[j][3], o0, o1);
                float2 cc = *(float2*)(crow + 2 * j);
                float cn0 = sig_(f0) * cc.x + sig_(i0) * tanh_(g0);
                float cn1 = sig_(f1) * cc.y + sig_(i1) * tanh_(g1);
                float h0 = sig_(o0) * tanh_(cn0);
                float h1 = sig_(o1) * tanh_(cn1);
                *(float2*)(crow + 2 * j) = make_float2(cn0, cn1);
                *(float2*)(hrow + 2 * j) = make_float2(h0, h1);
                ph[2 * j]     += h0 * dwu;
                ph[2 * j + 1] += h1 * dwu;
            }
        }

        // ---- dense head: reduce ph over the 32 unit-lanes of this warp ----
#pragma unroll
        for (int j = 0; j < 14; ++j) {
            float v = ph[j];
#pragma unroll
            for (int off = 16; off; off >>= 1)
                v += __shfl_xor_sync(0xffffffffu, v, off);
            if (lane == 0) Red[wrp * 16 + j] = v;
        }
        __syncthreads();

        if (tid < RPC) {
            int r = tid, rgg = r / 14, jr = r % 14;
            float pred = db0
                + Red[(rgg * 4 + 0) * 16 + jr] + Red[(rgg * 4 + 1) * 16 + jr]
                + Red[(rgg * 4 + 2) * 16 + jr] + Red[(rgg * 4 + 3) * 16 + jr];
            long gr = rowg0 + r;
            if (gr < 8192) out[gr * 64 + t] = pred;
            As[(64 + (t & 15)) * PIT + r] = pred;   // circular yp slot for step t
        }
        // next-iter staging writes rows 0..63 only; yp/h reads gated by syncA
    }
}

extern "C" void kernel_launch(void* const* d_in, const int* in_sizes, int n_in,
                              void* d_out, int out_size) {
    const float* x    = (const float*)d_in[0];
    const float* y0   = (const float*)d_in[1];
    const float* Wk   = (const float*)d_in[2];
    const float* Wr   = (const float*)d_in[3];
    const float* bias = (const float*)d_in[4];
    const float* dw   = (const float*)d_in[5];
    const float* db   = (const float*)d_in[6];
    float* out = (float*)d_out;

    static int smem_set = 0;
    const int smem_bytes = SM_FLOATS * 4;
    if (!smem_set) {
        cudaFuncSetAttribute(lstm_roll,
                             cudaFuncAttributeMaxDynamicSharedMemorySize,
                             smem_bytes);
        smem_set = 1;
    }
    presplat<<<336, 1024>>>(Wk, Wr, bias);
    lstm_roll<<<NCTA, NTHR, smem_bytes>>>(x, y0, dw, db, out);
}

// round 6
// speedup vs baseline: 1.9590x; 1.3005x over previous
#include <cuda_runtime.h>

// LSTM rollout v3: row-pair f32x2, unsplatted-weight LDG.128 + register splat,
// slot-padded activation rows for LDS.128.
// B=8192, T=64, F=64, ORD=16, K=256. 147 CTAs x 512 thr, 56 rows/CTA.
// Thread = (rg 0..3: 14 rows in 16 slots) x (c 0..127); 2 passes over units.

#define NCTA 147
#define NTHR 512
#define RPC  56
#define PIT  68            // k-row pitch (floats): 64 row-slots + 4 pad, 16B-aligned
#define PITC 58
typedef unsigned long long ull;

__device__ float g_Wf[336 * 1024];  // [k][u][g] plain float
__device__ ull   g_Bs[1024];        // [u][g] pre-splatted bias

#define AS_F (592 * PIT)   // k-rows: x 0..63 | yp 64..79 | h0 80..335 | h1 336..591
#define CS_F (256 * PITC)
#define SM_FLOATS (AS_F + CS_F + 256)

__device__ __forceinline__ ull splat2(float f) {
    unsigned u = __float_as_uint(f); ull r;
    asm("mov.b64 %0, {%1, %1};" : "=l"(r) : "r"(u));
    return r;
}
__device__ __forceinline__ void fma2(ull& d, ull a, ull b) {
    asm("fma.rn.f32x2 %0, %1, %2, %0;" : "+l"(d) : "l"(a), "l"(b));
}
__device__ __forceinline__ void unpack2(ull v, float& lo, float& hi) {
    unsigned a, b;
    asm("mov.b64 {%0, %1}, %2;" : "=r"(a), "=r"(b) : "l"(v));
    lo = __uint_as_float(a); hi = __uint_as_float(b);
}
__device__ __forceinline__ float fex2(float x) {
    float r; asm("ex2.approx.f32 %0, %1;" : "=f"(r) : "f"(x)); return r;
}
__device__ __forceinline__ float frcp(float x) {
    float r; asm("rcp.approx.f32 %0, %1;" : "=f"(r) : "f"(x));
    return fmaf(r, fmaf(-x, r, 1.0f), r);
}
__device__ __forceinline__ float sig_(float x) {
    x = fminf(30.f, fmaxf(-30.f, x));
    return frcp(1.0f + fex2(-1.4426950408889634f * x));
}
__device__ __forceinline__ float tanh_(float x) {
    x = fminf(30.f, fmaxf(-30.f, x));
    return fmaf(2.0f, frcp(1.0f + fex2(-2.8853900817779268f * x)), -1.0f);
}

// one k-step: 1 LDG.128 + 3 LDS.128 + 1 LDS.64 + 8 MOV + 28 FFMA2
__device__ __forceinline__ void kstep(ull (&acc)[7][4], const float* __restrict__ wp,
                                      const float* __restrict__ arow) {
    float4 w = *(const float4*)(wp);
    ull w0 = splat2(w.x), w1 = splat2(w.y), w2 = splat2(w.z), w3 = splat2(w.w);
    ulonglong2 p01 = *(const ulonglong2*)(arow);
    ulonglong2 p23 = *(const ulonglong2*)(arow + 4);
    ulonglong2 p45 = *(const ulonglong2*)(arow + 8);
    ull        p6  = *(const ull*)(arow + 12);
    fma2(acc[0][0], p01.x, w0); fma2(acc[0][1], p01.x, w1);
    fma2(acc[0][2], p01.x, w2); fma2(acc[0][3], p01.x, w3);
    fma2(acc[1][0], p01.y, w0); fma2(acc[1][1], p01.y, w1);
    fma2(acc[1][2], p01.y, w2); fma2(acc[1][3], p01.y, w3);
    fma2(acc[2][0], p23.x, w0); fma2(acc[2][1], p23.x, w1);
    fma2(acc[2][2], p23.x, w2); fma2(acc[2][3], p23.x, w3);
    fma2(acc[3][0], p23.y, w0); fma2(acc[3][1], p23.y, w1);
    fma2(acc[3][2], p23.y, w2); fma2(acc[3][3], p23.y, w3);
    fma2(acc[4][0], p45.x, w0); fma2(acc[4][1], p45.x, w1);
    fma2(acc[4][2], p45.x, w2); fma2(acc[4][3], p45.x, w3);
    fma2(acc[5][0], p45.y, w0); fma2(acc[5][1], p45.y, w1);
    fma2(acc[5][2], p45.y, w2); fma2(acc[5][3], p45.y, w3);
    fma2(acc[6][0], p6,    w0); fma2(acc[6][1], p6,    w1);
    fma2(acc[6][2], p6,    w2); fma2(acc[6][3], p6,    w3);
}

__global__ void presplat(const float* __restrict__ Wk, const float* __restrict__ Wr,
                         const float* __restrict__ bias) {
    int k = blockIdx.x;                  // 0..335
    int col = threadIdx.x;               // 0..1023
    int g = col >> 8, u = col & 255;
    float v = (k < 80) ? Wk[k * 1024 + col] : Wr[(k - 80) * 1024 + col];
    g_Wf[k * 1024 + u * 4 + g] = v;
    if (k == 0) g_Bs[u * 4 + g] = splat2(bias[col]);
}

__global__ void __launch_bounds__(NTHR, 1)
lstm_roll(const float* __restrict__ x, const float* __restrict__ y0,
          const float* __restrict__ dw, const float* __restrict__ db,
          float* __restrict__ out)
{
    extern __shared__ float sm[];
    float* As  = sm;
    float* Cs  = sm + AS_F;
    float* Red = sm + AS_F + CS_F;

    const int tid  = threadIdx.x;
    const int lane = tid & 31;
    const int wrp  = tid >> 5;
    const int c    = tid & 127;
    const int rg   = tid >> 7;           // 0..3
    const long rowg0 = (long)blockIdx.x * RPC;

    // ---- init ----
    for (int i = tid; i < CS_F; i += NTHR) Cs[i] = 0.f;
    for (int i = tid; i < 512 * PIT; i += NTHR) As[80 * PIT + i] = 0.f;
    for (int i = tid; i < 16 * PIT; i += NTHR) As[64 * PIT + i] = 0.f;
    __syncthreads();
    for (int i = tid; i < RPC * 16; i += NTHR) {
        int r = i >> 4, j = i & 15;
        int slot = (r / 14) * 16 + (r % 14);
        long gr = rowg0 + r;
        // at step t, logical yp[j] lives in k-row 64 + ((t-1-j)&15); init slot 15-j
        As[(64 + (15 - j)) * PIT + slot] = (gr < 8192) ? y0[gr * 16 + j] : 0.f;
    }
    const float dw0 = dw[c], dw1 = dw[128 + c];
    const float db0 = db[0];
    __syncthreads();

    for (int t = 0; t < 64; ++t) {
        const int cur = t & 1, nxt = cur ^ 1;

        // ---- stage x[:, t, :] transposed into k-rows 0..63 (slot layout) ----
        for (int i = tid; i < RPC * 16; i += NTHR) {
            int r = i >> 4, q4 = i & 15;
            int slot = (r / 14) * 16 + (r % 14);
            long gr = rowg0 + r;
            float4 v = make_float4(0.f, 0.f, 0.f, 0.f);
            if (gr < 8192) v = *(const float4*)(x + (gr * 64 + t) * 64 + q4 * 4);
            As[(q4 * 4 + 0) * PIT + slot] = v.x;
            As[(q4 * 4 + 1) * PIT + slot] = v.y;
            As[(q4 * 4 + 2) * PIT + slot] = v.z;
            As[(q4 * 4 + 3) * PIT + slot] = v.w;
        }
        __syncthreads();

        float ph[14];
#pragma unroll
        for (int j = 0; j < 14; ++j) ph[j] = 0.f;

#pragma unroll
        for (int pass = 0; pass < 2; ++pass) {
            const int u = pass * 128 + c;
            const float* wb = g_Wf + u * 4;
            ull acc[7][4];
            {
                ulonglong2 b01 = *(const ulonglong2*)(g_Bs + u * 4);
                ulonglong2 b23 = *(const ulonglong2*)(g_Bs + u * 4 + 2);
#pragma unroll
                for (int j = 0; j < 7; ++j) {
                    acc[j][0] = b01.x; acc[j][1] = b01.y;
                    acc[j][2] = b23.x; acc[j][3] = b23.y;
                }
            }
            const float* ab = As + rg * 16;

            // x segment
#pragma unroll 4
            for (int k = 0; k < 64; ++k)
                kstep(acc, wb + (size_t)k * 1024, ab + k * PIT);
            // yp segment (circular k-rows)
#pragma unroll
            for (int j = 0; j < 16; ++j) {
                int row = 64 + ((t - 1 - j) & 15);
                kstep(acc, wb + (size_t)(64 + j) * 1024, ab + row * PIT);
            }
            // h segment
            {
                const float* hb = ab + (80 + cur * 256) * PIT;
                const float* wh = wb + (size_t)80 * 1024;
#pragma unroll 4
                for (int k = 0; k < 256; ++k)
                    kstep(acc, wh + (size_t)k * 1024, hb + k * PIT);
            }

            // ---- gates + state update ----
            const float dwu = pass ? dw1 : dw0;
            float* crow = Cs + u * PITC + rg * 14;
            float* hrow = As + (80 + nxt * 256 + u) * PIT + rg * 16;
#pragma unroll
            for (int j = 0; j < 7; ++j) {
                float i0, i1, f0, f1, g0, g1, o0, o1;
                unpack2(acc[j][0], i0, i1);
                unpack2(acc[j][1], f0, f1);
                unpack2(acc[j][2], g0, g1);
                unpack2(acc[j][3], o0, o1);
                float2 cc = *(float2*)(crow + 2 * j);
                float cn0 = sig_(f0) * cc.x + sig_(i0) * tanh_(g0);
                float cn1 = sig_(f1) * cc.y + sig_(i1) * tanh_(g1);
                float h0 = sig_(o0) * tanh_(cn0);
                float h1 = sig_(o1) * tanh_(cn1);
                *(float2*)(crow + 2 * j) = make_float2(cn0, cn1);
                *(float2*)(hrow + 2 * j) = make_float2(h0, h1);
                ph[2 * j]     += h0 * dwu;
                ph[2 * j + 1] += h1 * dwu;
            }
        }

        // ---- dense head ----
#pragma unroll
        for (int j = 0; j < 14; ++j) {
            float v = ph[j];
#pragma unroll
            for (int off = 16; off; off >>= 1)
                v += __shfl_xor_sync(0xffffffffu, v, off);
            if (lane == 0) Red[wrp * 16 + j] = v;
        }
        __syncthreads();

        if (tid < RPC) {
            int r = tid, rgg = r / 14, jr = r % 14;
            float pred = db0
                + Red[(rgg * 4 + 0) * 16 + jr] + Red[(rgg * 4 + 1) * 16 + jr]
                + Red[(rgg * 4 + 2) * 16 + jr] + Red[(rgg * 4 + 3) * 16 + jr];
            long gr = rowg0 + r;
            if (gr < 8192) out[gr * 64 + t] = pred;
            int slot = rgg * 16 + jr;
            As[(64 + (t & 15)) * PIT + slot] = pred;  // yp slot for step t
        }
        // next-iter x staging writes k-rows 0..63 only; gated by its own sync
    }
}

extern "C" void kernel_launch(void* const* d_in, const int* in_sizes, int n_in,
                              void* d_out, int out_size) {
    const float* x    = (const float*)d_in[0];
    const float* y0   = (const float*)d_in[1];
    const float* Wk   = (const float*)d_in[2];
    const float* Wr   = (const float*)d_in[3];
    const float* bias = (const float*)d_in[4];
    const float* dw   = (const float*)d_in[5];
    const float* db   = (const float*)d_in[6];
    float* out = (float*)d_out;

    static int smem_set = 0;
    const int smem_bytes = SM_FLOATS * 4;
    if (!smem_set) {
        cudaFuncSetAttribute(lstm_roll,
                             cudaFuncAttributeMaxDynamicSharedMemorySize,
                             smem_bytes);
        smem_set = 1;
    }
    presplat<<<336, 1024>>>(Wk, Wr, bias);
    lstm_roll<<<NCTA, NTHR, smem_bytes>>>(x, y0, dw, db, out);
}

// round 7
// speedup vs baseline: 2.0504x; 1.0467x over previous
#include <cuda_runtime.h>

// LSTM rollout v3: row-pair f32x2, unsplatted-weight LDG.128 + register splat,
// slot-padded activation rows for LDS.128.
// B=8192, T=64, F=64, ORD=16, K=256. 147 CTAs x 512 thr, 56 rows/CTA.
// Thread = (rg 0..3: 14 rows in 16 slots) x (c 0..127); 2 passes over units.

#define NCTA 147
#define NTHR 512
#define RPC  56
#define PIT  68            // k-row pitch (floats): 64 row-slots + 4 pad, 16B-aligned
#define PITC 58
typedef unsigned long long ull;

__device__ float g_Wf[336 * 1024];  // [k][u][g] plain float
__device__ ull   g_Bs[1024];        // [u][g] pre-splatted bias

#define AS_F (592 * PIT)   // k-rows: x 0..63 | yp 64..79 | h0 80..335 | h1 336..591
#define CS_F (256 * PITC)
#define SM_FLOATS (AS_F + CS_F + 256)

__device__ __forceinline__ ull splat2(float f) {
    unsigned u = __float_as_uint(f); ull r;
    asm("mov.b64 %0, {%1, %1};" : "=l"(r) : "r"(u));
    return r;
}
__device__ __forceinline__ void fma2(ull& d, ull a, ull b) {
    asm("fma.rn.f32x2 %0, %1, %2, %0;" : "+l"(d) : "l"(a), "l"(b));
}
__device__ __forceinline__ void unpack2(ull v, float& lo, float& hi) {
    unsigned a, b;
    asm("mov.b64 {%0, %1}, %2;" : "=r"(a), "=r"(b) : "l"(v));
    lo = __uint_as_float(a); hi = __uint_as_float(b);
}
__device__ __forceinline__ float fex2(float x) {
    float r; asm("ex2.approx.f32 %0, %1;" : "=f"(r) : "f"(x)); return r;
}
__device__ __forceinline__ float frcp(float x) {
    float r; asm("rcp.approx.f32 %0, %1;" : "=f"(r) : "f"(x));
    return fmaf(r, fmaf(-x, r, 1.0f), r);
}
__device__ __forceinline__ float sig_(float x) {
    x = fminf(30.f, fmaxf(-30.f, x));
    return frcp(1.0f + fex2(-1.4426950408889634f * x));
}
__device__ __forceinline__ float tanh_(float x) {
    x = fminf(30.f, fmaxf(-30.f, x));
    return fmaf(2.0f, frcp(1.0f + fex2(-2.8853900817779268f * x)), -1.0f);
}

// one k-step: 1 LDG.128 + 3 LDS.128 + 1 LDS.64 + 8 MOV + 28 FFMA2
__device__ __forceinline__ void kstep(ull (&acc)[7][4], const float* __restrict__ wp,
                                      const float* __restrict__ arow) {
    float4 w = *(const float4*)(wp);
    ull w0 = splat2(w.x), w1 = splat2(w.y), w2 = splat2(w.z), w3 = splat2(w.w);
    ulonglong2 p01 = *(const ulonglong2*)(arow);
    ulonglong2 p23 = *(const ulonglong2*)(arow + 4);
    ulonglong2 p45 = *(const ulonglong2*)(arow + 8);
    ull        p6  = *(const ull*)(arow + 12);
    fma2(acc[0][0], p01.x, w0); fma2(acc[0][1], p01.x, w1);
    fma2(acc[0][2], p01.x, w2); fma2(acc[0][3], p01.x, w3);
    fma2(acc[1][0], p01.y, w0); fma2(acc[1][1], p01.y, w1);
    fma2(acc[1][2], p01.y, w2); fma2(acc[1][3], p01.y, w3);
    fma2(acc[2][0], p23.x, w0); fma2(acc[2][1], p23.x, w1);
    fma2(acc[2][2], p23.x, w2); fma2(acc[2][3], p23.x, w3);
    fma2(acc[3][0], p23.y, w0); fma2(acc[3][1], p23.y, w1);
    fma2(acc[3][2], p23.y, w2); fma2(acc[3][3], p23.y, w3);
    fma2(acc[4][0], p45.x, w0); fma2(acc[4][1], p45.x, w1);
    fma2(acc[4][2], p45.x, w2); fma2(acc[4][3], p45.x, w3);
    fma2(acc[5][0], p45.y, w0); fma2(acc[5][1], p45.y, w1);
    fma2(acc[5][2], p45.y, w2); fma2(acc[5][3], p45.y, w3);
    fma2(acc[6][0], p6,    w0); fma2(acc[6][1], p6,    w1);
    fma2(acc[6][2], p6,    w2); fma2(acc[6][3], p6,    w3);
}

__global__ void presplat(const float* __restrict__ Wk, const float* __restrict__ Wr,
                         const float* __restrict__ bias) {
    int k = blockIdx.x;                  // 0..335
    int col = threadIdx.x;               // 0..1023
    int g = col >> 8, u = col & 255;
    float v = (k < 80) ? Wk[k * 1024 + col] : Wr[(k - 80) * 1024 + col];
    g_Wf[k * 1024 + u * 4 + g] = v;
    if (k == 0) g_Bs[u * 4 + g] = splat2(bias[col]);
}

__global__ void __launch_bounds__(NTHR, 1)
lstm_roll(const float* __restrict__ x, const float* __restrict__ y0,
          const float* __restrict__ dw, const float* __restrict__ db,
          float* __restrict__ out)
{
    extern __shared__ float sm[];
    float* As  = sm;
    float* Cs  = sm + AS_F;
    float* Red = sm + AS_F + CS_F;

    const int tid  = threadIdx.x;
    const int lane = tid & 31;
    const int wrp  = tid >> 5;
    const int c    = tid & 127;
    const int rg   = tid >> 7;           // 0..3
    const long rowg0 = (long)blockIdx.x * RPC;

    // ---- init ----
    for (int i = tid; i < CS_F; i += NTHR) Cs[i] = 0.f;
    for (int i = tid; i < 512 * PIT; i += NTHR) As[80 * PIT + i] = 0.f;
    for (int i = tid; i < 16 * PIT; i += NTHR) As[64 * PIT + i] = 0.f;
    __syncthreads();
    for (int i = tid; i < RPC * 16; i += NTHR) {
        int r = i >> 4, j = i & 15;
        int slot = (r / 14) * 16 + (r % 14);
        long gr = rowg0 + r;
        // at step t, logical yp[j] lives in k-row 64 + ((t-1-j)&15); init slot 15-j
        As[(64 + (15 - j)) * PIT + slot] = (gr < 8192) ? y0[gr * 16 + j] : 0.f;
    }
    const float dw0 = dw[c], dw1 = dw[128 + c];
    const float db0 = db[0];
    __syncthreads();

    for (int t = 0; t < 64; ++t) {
        const int cur = t & 1, nxt = cur ^ 1;

        // ---- stage x[:, t, :] transposed into k-rows 0..63 (slot layout) ----
        for (int i = tid; i < RPC * 16; i += NTHR) {
            int r = i >> 4, q4 = i & 15;
            int slot = (r / 14) * 16 + (r % 14);
            long gr = rowg0 + r;
            float4 v = make_float4(0.f, 0.f, 0.f, 0.f);
            if (gr < 8192) v = *(const float4*)(x + (gr * 64 + t) * 64 + q4 * 4);
            As[(q4 * 4 + 0) * PIT + slot] = v.x;
            As[(q4 * 4 + 1) * PIT + slot] = v.y;
            As[(q4 * 4 + 2) * PIT + slot] = v.z;
            As[(q4 * 4 + 3) * PIT + slot] = v.w;
        }
        __syncthreads();

        float ph[14];
#pragma unroll
        for (int j = 0; j < 14; ++j) ph[j] = 0.f;

#pragma unroll
        for (int pass = 0; pass < 2; ++pass) {
            const int u = pass * 128 + c;
            const float* wb = g_Wf + u * 4;
            ull acc[7][4];
            {
                ulonglong2 b01 = *(const ulonglong2*)(g_Bs + u * 4);
                ulonglong2 b23 = *(const ulonglong2*)(g_Bs + u * 4 + 2);
#pragma unroll
                for (int j = 0; j < 7; ++j) {
                    acc[j][0] = b01.x; acc[j][1] = b01.y;
                    acc[j][2] = b23.x; acc[j][3] = b23.y;
                }
            }
            const float* ab = As + rg * 16;

            // x segment
#pragma unroll 4
            for (int k = 0; k < 64; ++k)
                kstep(acc, wb + (size_t)k * 1024, ab + k * PIT);
            // yp segment (circular k-rows)
#pragma unroll
            for (int j = 0; j < 16; ++j) {
                int row = 64 + ((t - 1 - j) & 15);
                kstep(acc, wb + (size_t)(64 + j) * 1024, ab + row * PIT);
            }
            // h segment
            {
                const float* hb = ab + (80 + cur * 256) * PIT;
                const float* wh = wb + (size_t)80 * 1024;
#pragma unroll 4
                for (int k = 0; k < 256; ++k)
                    kstep(acc, wh + (size_t)k * 1024, hb + k * PIT);
            }

            // ---- gates + state update ----
            const float dwu = pass ? dw1 : dw0;
            float* crow = Cs + u * PITC + rg * 14;
            float* hrow = As + (80 + nxt * 256 + u) * PIT + rg * 16;
#pragma unroll
            for (int j = 0; j < 7; ++j) {
                float i0, i1, f0, f1, g0, g1, o0, o1;
                unpack2(acc[j][0], i0, i1);
                unpack2(acc[j][1], f0, f1);
                unpack2(acc[j][2], g0, g1);
                unpack2(acc[j][3], o0, o1);
                float2 cc = *(float2*)(crow + 2 * j);
                float cn0 = sig_(f0) * cc.x + sig_(i0) * tanh_(g0);
                float cn1 = sig_(f1) * cc.y + sig_(i1) * tanh_(g1);
                float h0 = sig_(o0) * tanh_(cn0);
                float h1 = sig_(o1) * tanh_(cn1);
                *(float2*)(crow + 2 * j) = make_float2(cn0, cn1);
                *(float2*)(hrow + 2 * j) = make_float2(h0, h1);
                ph[2 * j]     += h0 * dwu;
                ph[2 * j + 1] += h1 * dwu;
            }
        }

        // ---- dense head ----
#pragma unroll
        for (int j = 0; j < 14; ++j) {
            float v = ph[j];
#pragma unroll
            for (int off = 16; off; off >>= 1)
                v += __shfl_xor_sync(0xffffffffu, v, off);
            if (lane == 0) Red[wrp * 16 + j] = v;
        }
        __syncthreads();

        if (tid < RPC) {
            int r = tid, rgg = r / 14, jr = r % 14;
            float pred = db0
                + Red[(rgg * 4 + 0) * 16 + jr] + Red[(rgg * 4 + 1) * 16 + jr]
                + Red[(rgg * 4 + 2) * 16 + jr] + Red[(rgg * 4 + 3) * 16 + jr];
            long gr = rowg0 + r;
            if (gr < 8192) out[gr * 64 + t] = pred;
            int slot = rgg * 16 + jr;
            As[(64 + (t & 15)) * PIT + slot] = pred;  // yp slot for step t
        }
        // next-iter x staging writes k-rows 0..63 only; gated by its own sync
    }
}

extern "C" void kernel_launch(void* const* d_in, const int* in_sizes, int n_in,
                              void* d_out, int out_size) {
    const float* x    = (const float*)d_in[0];
    const float* y0   = (const float*)d_in[1];
    const float* Wk   = (const float*)d_in[2];
    const float* Wr   = (const float*)d_in[3];
    const float* bias = (const float*)d_in[4];
    const float* dw   = (const float*)d_in[5];
    const float* db   = (const float*)d_in[6];
    float* out = (float*)d_out;

    static int smem_set = 0;
    const int smem_bytes = SM_FLOATS * 4;
    if (!smem_set) {
        cudaFuncSetAttribute(lstm_roll,
                             cudaFuncAttributeMaxDynamicSharedMemorySize,
                             smem_bytes);
        smem_set = 1;
    }
    presplat<<<336, 1024>>>(Wk, Wr, bias);
    lstm_roll<<<NCTA, NTHR, smem_bytes>>>(x, y0, dw, db, out);
}

// round 9
// speedup vs baseline: 3.9544x; 1.9286x over previous
#include <cuda_runtime.h>
#include <cuda_bf16.h>
#include <cstdint>

// LSTM rollout on mma.sync bf16 (hi/lo 3-split).
// B=8192, T=64, F=64, ORD=16, K=256. 128 CTAs x 256 thr, 64 rows/CTA.
// K-recur = 272 (yp 16 + h 256) = 17 k-chunks of 16.
// Per pass (2): N=512; 8 warps x 64 cols; C frags 4(mf) x 8(nf) per thread.

typedef unsigned u32;
typedef unsigned long long ull;

__device__ u32   g_Wfrag[2 * 17 * 8 * 8 * 32 * 4];  // recurrent B frags
__device__ u32   g_WXfrag[2 * 4 * 8 * 8 * 32 * 4];  // zx B frags
__device__ float g_ZxA[(size_t)1 << 28];            // pass0 C-init frags
__device__ float g_ZxB[(size_t)1 << 28];            // pass1

__device__ __forceinline__ float bhi_(float v) {
    return __bfloat162float(__float2bfloat16(v));
}
__device__ __forceinline__ u32 packh(float a, float b) {
    __nv_bfloat162 t;
    t.x = __float2bfloat16(a);
    t.y = __float2bfloat16(b);
    return *reinterpret_cast<u32*>(&t);
}
__device__ __forceinline__ float fex2(float x) {
    float r; asm("ex2.approx.f32 %0, %1;" : "=f"(r) : "f"(x)); return r;
}
__device__ __forceinline__ float frcp(float x) {
    float r; asm("rcp.approx.f32 %0, %1;" : "=f"(r) : "f"(x));
    return fmaf(r, fmaf(-x, r, 1.0f), r);
}
__device__ __forceinline__ float sig_(float x) {
    x = fminf(30.f, fmaxf(-30.f, x));
    return frcp(1.0f + fex2(-1.4426950408889634f * x));
}
__device__ __forceinline__ float tanh_(float x) {
    x = fminf(30.f, fmaxf(-30.f, x));
    return fmaf(2.0f, frcp(1.0f + fex2(-2.8853900817779268f * x)), -1.0f);
}
__device__ __forceinline__ void mma16816(float* c, const u32* a, const u32* b) {
    asm volatile(
        "mma.sync.aligned.m16n8k16.row.col.f32.bf16.bf16.f32 "
        "{%0,%1,%2,%3}, {%4,%5,%6,%7}, {%8,%9}, {%0,%1,%2,%3};"
        : "+f"(c[0]), "+f"(c[1]), "+f"(c[2]), "+f"(c[3])
        : "r"(a[0]), "r"(a[1]), "r"(a[2]), "r"(a[3]), "r"(b[0]), "r"(b[1]));
}

// ---------------- presplat: weights -> B-fragment order ----------------
// cell (P,kc,W,nf,L): k0 = kc*16+(L&3)*2; n-col q = L>>2:
//   u = P*128+W*16+(nf>>2)*8+q; col = (nf&3)*256+u
// regs: [bhi(k0,k0+1), bhi(k0+8,k0+9), blo(k0,k0+1), blo(k0+8,k0+9)]
__global__ void presplat(const float* __restrict__ Wk, const float* __restrict__ Wr) {
    int idx = blockIdx.x * 256 + threadIdx.x;
    int L = idx & 31, nf = (idx >> 5) & 7, W = (idx >> 8) & 7;
    float v[4];
    if (idx < 2 * 17 * 8 * 8 * 32) {
        int rem = idx >> 11, kc = rem % 17, P = rem / 17;
        int u = P * 128 + W * 16 + (nf >> 2) * 8 + (L >> 2);
        int col = (nf & 3) * 256 + u;
        int k0 = kc * 16 + (L & 3) * 2;
#pragma unroll
        for (int e = 0; e < 4; ++e) {
            int kg = k0 + (e >> 1) * 8 + (e & 1);
            v[e] = (kg < 16) ? Wk[(64 + kg) * 1024 + col]
                             : Wr[(kg - 16) * 1024 + col];
        }
        u32* d = g_Wfrag + (size_t)idx * 4;
        d[0] = packh(v[0], v[1]);
        d[1] = packh(v[2], v[3]);
        d[2] = packh(v[0] - bhi_(v[0]), v[1] - bhi_(v[1]));
        d[3] = packh(v[2] - bhi_(v[2]), v[3] - bhi_(v[3]));
    } else {
        int idx2 = idx - 2 * 17 * 8 * 8 * 32;
        if (idx2 >= 2 * 4 * 8 * 8 * 32) return;
        L = idx2 & 31; nf = (idx2 >> 5) & 7; W = (idx2 >> 8) & 7;
        int kc = (idx2 >> 11) & 3, P = idx2 >> 13;
        int u = P * 128 + W * 16 + (nf >> 2) * 8 + (L >> 2);
        int col = (nf & 3) * 256 + u;
        int k0 = kc * 16 + (L & 3) * 2;
#pragma unroll
        for (int e = 0; e < 4; ++e)
            v[e] = Wk[(k0 + (e >> 1) * 8 + (e & 1)) * 1024 + col];
        u32* d = g_WXfrag + (size_t)idx2 * 4;
        d[0] = packh(v[0], v[1]);
        d[1] = packh(v[2], v[3]);
        d[2] = packh(v[0] - bhi_(v[0]), v[1] - bhi_(v[1]));
        d[3] = packh(v[2] - bhi_(v[2]), v[3] - bhi_(v[3]));
    }
}

// ---------------- zx_gemm: Zx = x @ Wk[0:64] + bias ----------------
__global__ void __launch_bounds__(256, 1)
zx_gemm(const float* __restrict__ x, const float* __restrict__ bias)
{
    __shared__ u32 Axh[4 * 4 * 32 * 4];
    __shared__ u32 Axl[4 * 4 * 32 * 4];
    const int tid = threadIdx.x, W = tid >> 5, L = tid & 31;
    const int b0 = blockIdx.x * 64;

    float biasr[2][8][2];
#pragma unroll
    for (int P = 0; P < 2; ++P)
#pragma unroll
        for (int nf = 0; nf < 8; ++nf)
#pragma unroll
            for (int cc = 0; cc < 2; ++cc)
                biasr[P][nf][cc] = bias[(nf & 3) * 256 + P * 128 + W * 16
                                        + (nf >> 2) * 8 + (L & 3) * 2 + cc];

    for (int t = 0; t < 64; ++t) {
        // stage x rows b0..b0+63 (feature-major) into A-frag layout
#pragma unroll
        for (int i = 0; i < 4; ++i) {
            int q4 = tid + i * 256;          // 0..1023
            int r = q4 >> 4, fb = (q4 & 15) * 4;
            float4 v = *(const float4*)(x + ((size_t)(b0 + r) * 64 + t) * 64 + fb);
            float va[4] = {v.x, v.y, v.z, v.w};
#pragma unroll
            for (int p2 = 0; p2 < 2; ++p2) {
                int f0 = fb + p2 * 2;
                int kin = f0 & 15, kc = f0 >> 4;
                int Lw = (r & 7) * 4 + ((kin & 7) >> 1);
                int mf = r >> 4;
                int j = (((r & 15) >= 8) ? 1 : 0) + ((kin >= 8) ? 2 : 0);
                int cell = ((kc * 4 + mf) * 32 + Lw) * 4 + j;
                float a = va[p2 * 2], b = va[p2 * 2 + 1];
                Axh[cell] = packh(a, b);
                Axl[cell] = packh(a - bhi_(a), b - bhi_(b));
            }
        }
        __syncthreads();

#pragma unroll
        for (int P = 0; P < 2; ++P) {
            float C[4][8][4];
#pragma unroll
            for (int mf = 0; mf < 4; ++mf)
#pragma unroll
                for (int nf = 0; nf < 8; ++nf) {
                    C[mf][nf][0] = biasr[P][nf][0];
                    C[mf][nf][1] = biasr[P][nf][1];
                    C[mf][nf][2] = biasr[P][nf][0];
                    C[mf][nf][3] = biasr[P][nf][1];
                }
#pragma unroll
            for (int kc = 0; kc < 4; ++kc) {
                u32 B4[8][4];
#pragma unroll
                for (int nf = 0; nf < 8; ++nf)
                    *(uint4*)B4[nf] = *(const uint4*)(g_WXfrag
                        + ((size_t)(((P * 4 + kc) * 8 + W) * 8 + nf) * 32 + L) * 4);
#pragma unroll
                for (int mf = 0; mf < 4; ++mf) {
                    uint4 ah = *(const uint4*)(Axh + ((kc * 4 + mf) * 32 + L) * 4);
                    uint4 al = *(const uint4*)(Axl + ((kc * 4 + mf) * 32 + L) * 4);
#pragma unroll
                    for (int nf = 0; nf < 8; ++nf)
                        mma16816(C[mf][nf], (const u32*)&ah, &B4[nf][0]);
#pragma unroll
                    for (int nf = 0; nf < 8; ++nf)
                        mma16816(C[mf][nf], (const u32*)&ah, &B4[nf][2]);
#pragma unroll
                    for (int nf = 0; nf < 8; ++nf)
                        mma16816(C[mf][nf], (const u32*)&al, &B4[nf][0]);
                }
            }
            float* zx = P ? g_ZxB : g_ZxA;
            size_t ct = (size_t)b0 + t;      // == (blockIdx*64 + t)
#pragma unroll
            for (int mf = 0; mf < 4; ++mf)
#pragma unroll
                for (int nf = 0; nf < 8; ++nf)
                    *(float4*)(zx + ((((ct * 8 + W) * 4 + mf) * 8 + nf) * 32 + L) * 4)
                        = *(float4*)C[mf][nf];
        }
        __syncthreads();
    }
}

// ---------------- recurrent rollout on mma.sync ----------------
#define AHW (17 * 4 * 32 * 4)   // 8704 u32 per parity per hi/lo

__global__ void __launch_bounds__(256, 1)
lstm_mma(const float* __restrict__ y0, const float* __restrict__ dw,
         const float* __restrict__ db, float* __restrict__ out)
{
    extern __shared__ u32 smu[];
    u32* Ah = smu;                    // [2][AHW]
    u32* Al = smu + 2 * AHW;
    float* Cs    = (float*)(smu + 4 * AHW);   // [64][256]
    float* yring = Cs + 64 * 256;             // [16][64]
    float* red   = yring + 16 * 64;           // [64]

    const int tid = threadIdx.x, W = tid >> 5, L = tid & 31;
    const int b0 = blockIdx.x * 64;

    // init
    for (int i = tid; i < 2 * AHW; i += 256) { Ah[i] = 0u; Al[i] = 0u; }
    for (int i = tid; i < 64 * 256; i += 256) Cs[i] = 0.f;
    for (int i = tid; i < 1024; i += 256) {
        int j = i >> 6, r = i & 63;
        yring[(15 - j) * 64 + r] = y0[(size_t)(b0 + r) * 16 + j];
    }
    if (tid < 64) red[tid] = 0.f;

    float dwr[2][4];
#pragma unroll
    for (int P = 0; P < 2; ++P)
#pragma unroll
        for (int e = 0; e < 4; ++e)
            dwr[P][e] = dw[P * 128 + W * 16 + (e >> 1) * 8 + (L & 3) * 2 + (e & 1)];
    const float db0 = db[0];
    __syncthreads();

    // build yp k-chunk (kc=0) fragments for step tt into parity par
    auto buildYp = [&](int par, int tt) {
#pragma unroll
        for (int i = 0; i < 2; ++i) {
            int id = tid + i * 256;          // 0..511
            int r = id & 63, jp = id >> 6, j0 = jp * 2;
            float v0 = yring[((tt - 1 - j0) & 15) * 64 + r];
            float v1 = yring[((tt - 2 - j0) & 15) * 64 + r];
            int mf = r >> 4;
            int Lw = (r & 7) * 4 + ((j0 & 7) >> 1);
            int j = (((r & 15) >= 8) ? 1 : 0) + ((j0 >= 8) ? 2 : 0);
            int cell = par * AHW + (mf * 32 + Lw) * 4 + j;
            Ah[cell] = packh(v0, v1);
            Al[cell] = packh(v0 - bhi_(v0), v1 - bhi_(v1));
        }
    };
    buildYp(0, 0);
    __syncthreads();

    for (int t = 0; t < 64; ++t) {
        const int cur = t & 1, nxt = cur ^ 1;
        float part[8];
#pragma unroll
        for (int e = 0; e < 8; ++e) part[e] = 0.f;

#pragma unroll
        for (int P = 0; P < 2; ++P) {
            float C[4][8][4];
            const float* zx = P ? g_ZxB : g_ZxA;
            size_t ct = (size_t)b0 + t;
#pragma unroll
            for (int mf = 0; mf < 4; ++mf)
#pragma unroll
                for (int nf = 0; nf < 8; ++nf)
                    *(float4*)C[mf][nf] = *(const float4*)(zx
                        + ((((ct * 8 + W) * 4 + mf) * 8 + nf) * 32 + L) * 4);

            for (int kc = 0; kc < 17; ++kc) {
                u32 B4[8][4];
#pragma unroll
                for (int nf = 0; nf < 8; ++nf)
                    *(uint4*)B4[nf] = *(const uint4*)(g_Wfrag
                        + ((size_t)(((P * 17 + kc) * 8 + W) * 8 + nf) * 32 + L) * 4);
#pragma unroll
                for (int mf = 0; mf < 4; ++mf) {
                    uint4 ah = *(const uint4*)(Ah + cur * AHW + ((kc * 4 + mf) * 32 + L) * 4);
                    uint4 al = *(const uint4*)(Al + cur * AHW + ((kc * 4 + mf) * 32 + L) * 4);
#pragma unroll
                    for (int nf = 0; nf < 8; ++nf)
                        mma16816(C[mf][nf], (const u32*)&ah, &B4[nf][0]);
#pragma unroll
                    for (int nf = 0; nf < 8; ++nf)
                        mma16816(C[mf][nf], (const u32*)&ah, &B4[nf][2]);
#pragma unroll
                    for (int nf = 0; nf < 8; ++nf)
                        mma16816(C[mf][nf], (const u32*)&al, &B4[nf][0]);
                }
            }

            // gates + h write (A-frag layout, k-chunk kcA owned by this warp/pass)
            const int kcA = 1 + P * 8 + W;
#pragma unroll
            for (int mf = 0; mf < 4; ++mf) {
                float hv[2][2][2];   // [uh][jr][cc]
#pragma unroll
                for (int uh = 0; uh < 2; ++uh)
#pragma unroll
                    for (int jr = 0; jr < 2; ++jr) {
                        int r = mf * 16 + (L >> 2) + jr * 8;
#pragma unroll
                        for (int cc = 0; cc < 2; ++cc) {
                            float zi = C[mf][uh * 4 + 0][jr * 2 + cc];
                            float zf = C[mf][uh * 4 + 1][jr * 2 + cc];
                            float zg = C[mf][uh * 4 + 2][jr * 2 + cc];
                            float zo = C[mf][uh * 4 + 3][jr * 2 + cc];
                            int u = P * 128 + W * 16 + uh * 8 + (L & 3) * 2 + cc;
                            float co = Cs[r * 256 + u];
                            float cn = sig_(zf) * co + sig_(zi) * tanh_(zg);
                            float h = sig_(zo) * tanh_(cn);
                            Cs[r * 256 + u] = cn;
                            hv[uh][jr][cc] = h;
                            part[mf * 2 + jr] += h * dwr[P][uh * 2 + cc];
                        }
                    }
                u32 hh[4], hl[4];
#pragma unroll
                for (int uh = 0; uh < 2; ++uh)
#pragma unroll
                    for (int jr = 0; jr < 2; ++jr) {
                        float a = hv[uh][jr][0], b = hv[uh][jr][1];
                        hh[jr + 2 * uh] = packh(a, b);
                        hl[jr + 2 * uh] = packh(a - bhi_(a), b - bhi_(b));
                    }
                *(uint4*)(Ah + nxt * AHW + ((kcA * 4 + mf) * 32 + L) * 4)
                    = make_uint4(hh[0], hh[1], hh[2], hh[3]);
                *(uint4*)(Al + nxt * AHW + ((kcA * 4 + mf) * 32 + L) * 4)
                    = make_uint4(hl[0], hl[1], hl[2], hl[3]);
            }
        }

#pragma unroll
        for (int mf = 0; mf < 4; ++mf)
#pragma unroll
            for (int jr = 0; jr < 2; ++jr)
                atomicAdd(&red[mf * 16 + (L >> 2) + jr * 8], part[mf * 2 + jr]);
        __syncthreads();

        if (tid < 64) {
            float pred = red[tid] + db0;
            out[(size_t)(b0 + tid) * 64 + t] = pred;
            yring[(t & 15) * 64 + tid] = pred;
            red[tid] = 0.f;
        }
        __syncthreads();
        if (t < 63) {
            buildYp(nxt, t + 1);
            __syncthreads();
        }
    }
}

extern "C" void kernel_launch(void* const* d_in, const int* in_sizes, int n_in,
                              void* d_out, int out_size) {
    const float* x    = (const float*)d_in[0];
    const float* y0   = (const float*)d_in[1];
    const float* Wk   = (const float*)d_in[2];
    const float* Wr   = (const float*)d_in[3];
    const float* bias = (const float*)d_in[4];
    const float* dw   = (const float*)d_in[5];
    const float* db   = (const float*)d_in[6];
    float* out = (float*)d_out;

    const int smem_bytes = (4 * AHW) * 4 + (64 * 256 + 16 * 64 + 64) * 4;  // 209152
    static int done = 0;
    if (!done) {
        cudaFuncSetAttribute(lstm_mma,
                             cudaFuncAttributeMaxDynamicSharedMemorySize, smem_bytes);
        done = 1;
    }
    presplat<<<336, 256>>>(Wk, Wr);
    zx_gemm<<<128, 256>>>(x, bias);
    lstm_mma<<<128, 256, smem_bytes>>>(y0, dw, db, out);
}

// round 11
// speedup vs baseline: 4.4861x; 1.1345x over previous
#include <cuda_runtime.h>
#include <cuda_bf16.h>
#include <cstdint>

// LSTM rollout on mma.sync bf16 (hi/lo 3-split), software-pipelined.
// B=8192, T=64, F=64, ORD=16, K=256. 128 CTAs x 256 thr, 64 rows/CTA.
// K-recur = 272 (yp 16 + h 256) = 17 k-chunks of 16.

typedef unsigned u32;

__device__ u32   g_Wfrag[2 * 17 * 8 * 8 * 32 * 4];  // recurrent B frags
__device__ u32   g_WXfrag[2 * 4 * 8 * 8 * 32 * 4];  // zx B frags
__device__ float g_ZxA[(size_t)1 << 28];            // pass0 C-init frags
__device__ float g_ZxB[(size_t)1 << 28];            // pass1

__device__ __forceinline__ float bhi_(float v) {
    return __bfloat162float(__float2bfloat16(v));
}
__device__ __forceinline__ u32 packh(float a, float b) {
    __nv_bfloat162 t;
    t.x = __float2bfloat16(a);
    t.y = __float2bfloat16(b);
    return *reinterpret_cast<u32*>(&t);
}
__device__ __forceinline__ float fex2(float x) {
    float r; asm("ex2.approx.f32 %0, %1;" : "=f"(r) : "f"(x)); return r;
}
__device__ __forceinline__ float frcp(float x) {
    float r; asm("rcp.approx.f32 %0, %1;" : "=f"(r) : "f"(x));
    return fmaf(r, fmaf(-x, r, 1.0f), r);
}
__device__ __forceinline__ float sig_(float x) {
    x = fminf(30.f, fmaxf(-30.f, x));
    return frcp(1.0f + fex2(-1.4426950408889634f * x));
}
__device__ __forceinline__ float tanh_(float x) {
    x = fminf(30.f, fmaxf(-30.f, x));
    return fmaf(2.0f, frcp(1.0f + fex2(-2.8853900817779268f * x)), -1.0f);
}
__device__ __forceinline__ void mma16816(float* c, const u32* a, const u32* b) {
    asm volatile(
        "mma.sync.aligned.m16n8k16.row.col.f32.bf16.bf16.f32 "
        "{%0,%1,%2,%3}, {%4,%5,%6,%7}, {%8,%9}, {%0,%1,%2,%3};"
        : "+f"(c[0]), "+f"(c[1]), "+f"(c[2]), "+f"(c[3])
        : "r"(a[0]), "r"(a[1]), "r"(a[2]), "r"(a[3]), "r"(b[0]), "r"(b[1]));
}
__device__ __forceinline__ void pref_l2(const void* p) {
    asm volatile("prefetch.global.L2 [%0];" :: "l"(p));
}

// ---------------- presplat: weights -> B-fragment order ----------------
__global__ void presplat(const float* __restrict__ Wk, const float* __restrict__ Wr) {
    int idx = blockIdx.x * 256 + threadIdx.x;
    int L = idx & 31, nf = (idx >> 5) & 7, W = (idx >> 8) & 7;
    float v[4];
    if (idx < 2 * 17 * 8 * 8 * 32) {
        int rem = idx >> 11, kc = rem % 17, P = rem / 17;
        int u = P * 128 + W * 16 + (nf >> 2) * 8 + (L >> 2);
        int col = (nf & 3) * 256 + u;
        int k0 = kc * 16 + (L & 3) * 2;
#pragma unroll
        for (int e = 0; e < 4; ++e) {
            int kg = k0 + (e >> 1) * 8 + (e & 1);
            v[e] = (kg < 16) ? Wk[(64 + kg) * 1024 + col]
                             : Wr[(kg - 16) * 1024 + col];
        }
        u32* d = g_Wfrag + (size_t)idx * 4;
        d[0] = packh(v[0], v[1]);
        d[1] = packh(v[2], v[3]);
        d[2] = packh(v[0] - bhi_(v[0]), v[1] - bhi_(v[1]));
        d[3] = packh(v[2] - bhi_(v[2]), v[3] - bhi_(v[3]));
    } else {
        int idx2 = idx - 2 * 17 * 8 * 8 * 32;
        if (idx2 >= 2 * 4 * 8 * 8 * 32) return;
        L = idx2 & 31; nf = (idx2 >> 5) & 7; W = (idx2 >> 8) & 7;
        int kc = (idx2 >> 11) & 3, P = idx2 >> 13;
        int u = P * 128 + W * 16 + (nf >> 2) * 8 + (L >> 2);
        int col = (nf & 3) * 256 + u;
        int k0 = kc * 16 + (L & 3) * 2;
#pragma unroll
        for (int e = 0; e < 4; ++e)
            v[e] = Wk[(k0 + (e >> 1) * 8 + (e & 1)) * 1024 + col];
        u32* d = g_WXfrag + (size_t)idx2 * 4;
        d[0] = packh(v[0], v[1]);
        d[1] = packh(v[2], v[3]);
        d[2] = packh(v[0] - bhi_(v[0]), v[1] - bhi_(v[1]));
        d[3] = packh(v[2] - bhi_(v[2]), v[3] - bhi_(v[3]));
    }
}

// ---------------- zx_gemm: Zx = x @ Wk[0:64] + bias ----------------
__global__ void __launch_bounds__(256, 1)
zx_gemm(const float* __restrict__ x, const float* __restrict__ bias)
{
    __shared__ u32 Axh[4 * 4 * 32 * 4];
    __shared__ u32 Axl[4 * 4 * 32 * 4];
    const int tid = threadIdx.x, W = tid >> 5, L = tid & 31;
    const int b0 = blockIdx.x * 64;

    float biasr[2][8][2];
#pragma unroll
    for (int P = 0; P < 2; ++P)
#pragma unroll
        for (int nf = 0; nf < 8; ++nf)
#pragma unroll
            for (int cc = 0; cc < 2; ++cc)
                biasr[P][nf][cc] = bias[(nf & 3) * 256 + P * 128 + W * 16
                                        + (nf >> 2) * 8 + (L & 3) * 2 + cc];

    for (int t = 0; t < 64; ++t) {
#pragma unroll
        for (int i = 0; i < 4; ++i) {
            int q4 = tid + i * 256;
            int r = q4 >> 4, fb = (q4 & 15) * 4;
            const float* xp = x + ((size_t)(b0 + r) * 64 + t) * 64 + fb;
            float4 v = *(const float4*)xp;
            if (t < 63) pref_l2(xp + 64);
            float va[4] = {v.x, v.y, v.z, v.w};
#pragma unroll
            for (int p2 = 0; p2 < 2; ++p2) {
                int f0 = fb + p2 * 2;
                int kin = f0 & 15, kc = f0 >> 4;
                int Lw = (r & 7) * 4 + ((kin & 7) >> 1);
                int mf = r >> 4;
                int j = (((r & 15) >= 8) ? 1 : 0) + ((kin >= 8) ? 2 : 0);
                int cell = ((kc * 4 + mf) * 32 + Lw) * 4 + j;
                float a = va[p2 * 2], b = va[p2 * 2 + 1];
                Axh[cell] = packh(a, b);
                Axl[cell] = packh(a - bhi_(a), b - bhi_(b));
            }
        }
        __syncthreads();

#pragma unroll
        for (int P = 0; P < 2; ++P) {
            float C[4][8][4];
#pragma unroll
            for (int mf = 0; mf < 4; ++mf)
#pragma unroll
                for (int nf = 0; nf < 8; ++nf) {
                    C[mf][nf][0] = biasr[P][nf][0];
                    C[mf][nf][1] = biasr[P][nf][1];
                    C[mf][nf][2] = biasr[P][nf][0];
                    C[mf][nf][3] = biasr[P][nf][1];
                }

            u32 Ba[8][4], Bb[8][4];
            auto loadB = [&](u32 (&B)[8][4], int kc) {
#pragma unroll
                for (int nf = 0; nf < 8; ++nf)
                    *(uint4*)B[nf] = *(const uint4*)(g_WXfrag
                        + ((size_t)(((P * 4 + kc) * 8 + W) * 8 + nf) * 32 + L) * 4);
            };
            auto comp = [&](const u32 (&B)[8][4], int kc) {
#pragma unroll
                for (int mf = 0; mf < 4; ++mf) {
                    uint4 ah = *(const uint4*)(Axh + ((kc * 4 + mf) * 32 + L) * 4);
                    uint4 al = *(const uint4*)(Axl + ((kc * 4 + mf) * 32 + L) * 4);
#pragma unroll
                    for (int nf = 0; nf < 8; ++nf)
                        mma16816(C[mf][nf], (const u32*)&ah, &B[nf][0]);
#pragma unroll
                    for (int nf = 0; nf < 8; ++nf)
                        mma16816(C[mf][nf], (const u32*)&ah, &B[nf][2]);
#pragma unroll
                    for (int nf = 0; nf < 8; ++nf)
                        mma16816(C[mf][nf], (const u32*)&al, &B[nf][0]);
                }
            };
            loadB(Ba, 0);
            loadB(Bb, 1); comp(Ba, 0);
            loadB(Ba, 2); comp(Bb, 1);
            loadB(Bb, 3); comp(Ba, 2);
            comp(Bb, 3);

            float* zx = P ? g_ZxB : g_ZxA;
            size_t ct = (size_t)b0 + t;
#pragma unroll
            for (int mf = 0; mf < 4; ++mf)
#pragma unroll
                for (int nf = 0; nf < 8; ++nf)
                    *(float4*)(zx + ((((ct * 8 + W) * 4 + mf) * 8 + nf) * 32 + L) * 4)
                        = *(float4*)C[mf][nf];
        }
        __syncthreads();
    }
}

// ---------------- recurrent rollout on mma.sync ----------------
#define AHW (17 * 4 * 32 * 4)   // 8704 u32 per parity per hi/lo

__global__ void __launch_bounds__(256, 1)
lstm_mma(const float* __restrict__ y0, const float* __restrict__ dw,
         const float* __restrict__ db, float* __restrict__ out)
{
    extern __shared__ u32 smu[];
    u32* Ah = smu;                            // [2][AHW]
    u32* Al = smu + 2 * AHW;
    float* Cs    = (float*)(smu + 4 * AHW);   // [64][256]
    float* yring = Cs + 64 * 256;             // [16][64]
    float* redW  = yring + 16 * 64;           // [8][64]

    const int tid = threadIdx.x, W = tid >> 5, L = tid & 31;
    const int b0 = blockIdx.x * 64;

    for (int i = tid; i < 2 * AHW; i += 256) { Ah[i] = 0u; Al[i] = 0u; }
    for (int i = tid; i < 64 * 256; i += 256) Cs[i] = 0.f;
    for (int i = tid; i < 1024; i += 256) {
        int j = i >> 6, r = i & 63;
        yring[(15 - j) * 64 + r] = y0[(size_t)(b0 + r) * 16 + j];
    }

    float dwr[2][4];
#pragma unroll
    for (int P = 0; P < 2; ++P)
#pragma unroll
        for (int e = 0; e < 4; ++e)
            dwr[P][e] = dw[P * 128 + W * 16 + (e >> 1) * 8 + (L & 3) * 2 + (e & 1)];
    const float db0 = db[0];
    __syncthreads();

    auto buildYp = [&](int par, int tt) {
#pragma unroll
        for (int i = 0; i < 2; ++i) {
            int id = tid + i * 256;
            int r = id & 63, jp = id >> 6, j0 = jp * 2;
            float v0 = yring[((tt - 1 - j0) & 15) * 64 + r];
            float v1 = yring[((tt - 2 - j0) & 15) * 64 + r];
            int mf = r >> 4;
            int Lw = (r & 7) * 4 + ((j0 & 7) >> 1);
            int j = (((r & 15) >= 8) ? 1 : 0) + ((j0 >= 8) ? 2 : 0);
            int cell = par * AHW + (mf * 32 + Lw) * 4 + j;
            Ah[cell] = packh(v0, v1);
            Al[cell] = packh(v0 - bhi_(v0), v1 - bhi_(v1));
        }
    };
    buildYp(0, 0);
    __syncthreads();

    for (int t = 0; t < 64; ++t) {
        const int cur = t & 1, nxt = cur ^ 1;
        float part[8];
#pragma unroll
        for (int e = 0; e < 8; ++e) part[e] = 0.f;

#pragma unroll
        for (int P = 0; P < 2; ++P) {
            float C[4][8][4];
            const float* zx = P ? g_ZxB : g_ZxA;
            size_t ct = (size_t)b0 + t;
#pragma unroll
            for (int mf = 0; mf < 4; ++mf)
#pragma unroll
                for (int nf = 0; nf < 8; ++nf) {
                    const float* zp = zx
                        + ((((ct * 8 + W) * 4 + mf) * 8 + nf) * 32 + L) * 4;
                    *(float4*)C[mf][nf] = *(const float4*)zp;
                    // ct -> ct+1 advances the layout by 8*4*8*32*4 = 32768 floats / 4
                    // per (W,mf,nf,L) slot == 8192 floats from this thread's address.
                    if (t < 63) pref_l2(zp + 8192);
                }

            u32 Ba[8][4], Bb[8][4];
            auto loadB = [&](u32 (&B)[8][4], int kc) {
#pragma unroll
                for (int nf = 0; nf < 8; ++nf)
                    *(uint4*)B[nf] = *(const uint4*)(g_Wfrag
                        + ((size_t)(((P * 17 + kc) * 8 + W) * 8 + nf) * 32 + L) * 4);
            };
            auto comp = [&](const u32 (&B)[8][4], int kc) {
#pragma unroll
                for (int mf = 0; mf < 4; ++mf) {
                    uint4 ah = *(const uint4*)(Ah + cur * AHW + ((kc * 4 + mf) * 32 + L) * 4);
                    uint4 al = *(const uint4*)(Al + cur * AHW + ((kc * 4 + mf) * 32 + L) * 4);
#pragma unroll
                    for (int nf = 0; nf < 8; ++nf)
                        mma16816(C[mf][nf], (const u32*)&ah, &B[nf][0]);
#pragma unroll
                    for (int nf = 0; nf < 8; ++nf)
                        mma16816(C[mf][nf], (const u32*)&ah, &B[nf][2]);
#pragma unroll
                    for (int nf = 0; nf < 8; ++nf)
                        mma16816(C[mf][nf], (const u32*)&al, &B[nf][0]);
                }
            };
            loadB(Ba, 0);
#pragma unroll 1
            for (int s = 0; s < 8; ++s) {
                loadB(Bb, 2 * s + 1);
                comp(Ba, 2 * s);
                loadB(Ba, 2 * s + 2);
                comp(Bb, 2 * s + 1);
            }
            comp(Ba, 16);

            // gates + h write
            const int kcA = 1 + P * 8 + W;
#pragma unroll
            for (int mf = 0; mf < 4; ++mf) {
                float hv[2][2][2];
#pragma unroll
                for (int uh = 0; uh < 2; ++uh)
#pragma unroll
                    for (int jr = 0; jr < 2; ++jr) {
                        int r = mf * 16 + (L >> 2) + jr * 8;
#pragma unroll
                        for (int cc = 0; cc < 2; ++cc) {
                            float zi = C[mf][uh * 4 + 0][jr * 2 + cc];
                            float zf = C[mf][uh * 4 + 1][jr * 2 + cc];
                            float zg = C[mf][uh * 4 + 2][jr * 2 + cc];
                            float zo = C[mf][uh * 4 + 3][jr * 2 + cc];
                            int u = P * 128 + W * 16 + uh * 8 + (L & 3) * 2 + cc;
                            float co = Cs[r * 256 + u];
                            float cn = sig_(zf) * co + sig_(zi) * tanh_(zg);
                            float h = sig_(zo) * tanh_(cn);
                            Cs[r * 256 + u] = cn;
                            hv[uh][jr][cc] = h;
                            part[mf * 2 + jr] += h * dwr[P][uh * 2 + cc];
                        }
                    }
                u32 hh[4], hl[4];
#pragma unroll
                for (int uh = 0; uh < 2; ++uh)
#pragma unroll
                    for (int jr = 0; jr < 2; ++jr) {
                        float a = hv[uh][jr][0], b = hv[uh][jr][1];
                        hh[jr + 2 * uh] = packh(a, b);
                        hl[jr + 2 * uh] = packh(a - bhi_(a), b - bhi_(b));
                    }
                *(uint4*)(Ah + nxt * AHW + ((kcA * 4 + mf) * 32 + L) * 4)
                    = make_uint4(hh[0], hh[1], hh[2], hh[3]);
                *(uint4*)(Al + nxt * AHW + ((kcA * 4 + mf) * 32 + L) * 4)
                    = make_uint4(hl[0], hl[1], hl[2], hl[3]);
            }
        }

        // per-warp shfl reduction, then smem slot write (no atomics)
#pragma unroll
        for (int e = 0; e < 8; ++e) {
            float v = part[e];
            v += __shfl_xor_sync(0xffffffffu, v, 1);
            v += __shfl_xor_sync(0xffffffffu, v, 2);
            if ((L & 3) == 0) {
                int mf = e >> 1, jr = e & 1;
                redW[W * 64 + mf * 16 + (L >> 2) + jr * 8] = v;
            }
        }
        __syncthreads();

        if (tid < 64) {
            float pred = db0;
#pragma unroll
            for (int w = 0; w < 8; ++w) pred += redW[w * 64 + tid];
            out[(size_t)(b0 + tid) * 64 + t] = pred;
            yring[(t & 15) * 64 + tid] = pred;
        }
        __syncthreads();
        if (t < 63) {
            buildYp(nxt, t + 1);
            __syncthreads();
        }
    }
}

extern "C" void kernel_launch(void* const* d_in, const int* in_sizes, int n_in,
                              void* d_out, int out_size) {
    const float* x    = (const float*)d_in[0];
    const float* y0   = (const float*)d_in[1];
    const float* Wk   = (const float*)d_in[2];
    const float* Wr   = (const float*)d_in[3];
    const float* bias = (const float*)d_in[4];
    const float* dw   = (const float*)d_in[5];
    const float* db   = (const float*)d_in[6];
    float* out = (float*)d_out;

    const int smem_bytes = (4 * AHW) * 4 + (64 * 256 + 16 * 64 + 8 * 64) * 4;
    static int done = 0;
    if (!done) {
        cudaFuncSetAttribute(lstm_mma,
                             cudaFuncAttributeMaxDynamicSharedMemorySize, smem_bytes);
        done = 1;
    }
    presplat<<<336, 256>>>(Wk, Wr);
    zx_gemm<<<128, 256>>>(x, bias);
    lstm_mma<<<128, 256, smem_bytes>>>(y0, dw, db, out);
}